// round 6
// baseline (speedup 1.0000x reference)
#include <cuda_runtime.h>
#include <math.h>

#define N_ROWS  32768
#define D_DIM   256
#define K_CODES 4096

// Scratch (no allocations allowed): device globals.
__device__ float        g_eNorm[K_CODES];
__device__ float        g_xNorm[N_ROWS];
__device__ int          g_idx[N_ROWS];
__device__ unsigned int g_hist[K_CODES];
__device__ double       g_sse[256];

// ---------------------------------------------------------------------------
// Reset accumulated scratch (graph replays must be deterministic)
// ---------------------------------------------------------------------------
__global__ void reset_kernel() {
    int t = blockIdx.x * blockDim.x + threadIdx.x;
    for (int k = t; k < K_CODES; k += gridDim.x * blockDim.x) g_hist[k] = 0u;
    if (t < 256) g_sse[t] = 0.0;
}

// ---------------------------------------------------------------------------
// xNorm[n] = sum_d x[n][d]^2 — emulates XLA GPU row reduction: one warp per
// row, float2-vectorized loads (stride 64 cols), per-vector-lane accumulators
// combined at the end, then shfl_down tree 16,8,4,2,1. mul+add, no fma.
// (1-ulp deviations are harmless: they shift all rounding buckets uniformly.)
// ---------------------------------------------------------------------------
__global__ void xnorm_kernel(const float* __restrict__ x) {
    int warp = (blockIdx.x * blockDim.x + threadIdx.x) >> 5;
    int lane = threadIdx.x & 31;
    if (warp >= N_ROWS) return;
    const float2* xr = reinterpret_cast<const float2*>(x + (size_t)warp * D_DIM);
    float a0 = 0.f, a1 = 0.f;
    #pragma unroll
    for (int j = 0; j < 4; j++) {
        float2 v = xr[j * 32 + lane];
        a0 = __fadd_rn(a0, __fmul_rn(v.x, v.x));
        a1 = __fadd_rn(a1, __fmul_rn(v.y, v.y));
    }
    float s = __fadd_rn(a0, a1);
    #pragma unroll
    for (int o = 16; o; o >>= 1)
        s = __fadd_rn(s, __shfl_down_sync(0xffffffffu, s, o));
    if (lane == 0) g_xNorm[warp] = s;
}

// ---------------------------------------------------------------------------
// eNorm[k] = sum_d emb[k][d]^2 — value ~5e-6, entirely below half-ulp of
// xNorm (~256): fl(xNorm+eNorm)==xNorm, so order is irrelevant here.
// ---------------------------------------------------------------------------
__global__ void enorm_kernel(const float* __restrict__ emb) {
    int warp = (blockIdx.x * blockDim.x + threadIdx.x) >> 5;
    int lane = threadIdx.x & 31;
    if (warp >= K_CODES) return;
    const float2* er = reinterpret_cast<const float2*>(emb + (size_t)warp * D_DIM);
    float a0 = 0.f, a1 = 0.f;
    #pragma unroll
    for (int j = 0; j < 4; j++) {
        float2 v = er[j * 32 + lane];
        a0 = __fadd_rn(a0, __fmul_rn(v.x, v.x));
        a1 = __fadd_rn(a1, __fmul_rn(v.y, v.y));
    }
    float s = __fadd_rn(a0, a1);
    #pragma unroll
    for (int o = 16; o; o >>= 1)
        s = __fadd_rn(s, __shfl_down_sync(0xffffffffu, s, o));
    if (lane == 0) g_eNorm[warp] = s;
}

// ---------------------------------------------------------------------------
// Main kernel: per row n, argmin_k fl( fl(xNorm+eNorm) - 2 * dot ) with
// FULL fp32 dot (reference matmul is plain fp32 SGEMM — TF32 disproven in
// R3). 128x128 tile, BK=8, 256 threads, 8x8 register tile, double-buffered
// smem, transposed +4-padded tiles (conflict-free STS, aligned LDS.128).
// ---------------------------------------------------------------------------
__global__ void __launch_bounds__(256, 2)
argmin_kernel(const float* __restrict__ x, const float* __restrict__ emb) {
    constexpr int BM = 128, BN = 128, BK = 8;
    constexpr int LD = BM + 4;

    __shared__ union {
        struct { float As[2][BK][LD]; float Bs[2][BK][LD]; } t;
        struct { float redD[BM][17];  int   redI[BM][17]; }  r;
    } sm;

    const int tid = threadIdx.x;
    const int tx  = tid & 15;               // code group  (0..15) -> 8 codes
    const int ty  = tid >> 4;               // row  group  (0..15) -> 8 rows
    const int rowBase = blockIdx.x * BM;

    const int aRow = tid >> 1;              // 0..127
    const int aCol = (tid & 1) * 4;         // 0 or 4

    float bestD[8];
    int   bestI[8];
    float xn[8];
    #pragma unroll
    for (int i = 0; i < 8; i++) {
        bestD[i] = INFINITY; bestI[i] = 0;
        xn[i] = g_xNorm[rowBase + ty * 8 + i];
    }

    const float* xptr = x + (size_t)(rowBase + aRow) * D_DIM + aCol;

    for (int ct = 0; ct < K_CODES / BN; ++ct) {
        const float* eptr = emb + (size_t)(ct * BN + aRow) * D_DIM + aCol;

        float acc[8][8];
        #pragma unroll
        for (int i = 0; i < 8; i++)
            #pragma unroll
            for (int j = 0; j < 8; j++) acc[i][j] = 0.f;

        // ---- preload chunk 0 into buffer 0 ----
        float4 av = *reinterpret_cast<const float4*>(xptr);
        float4 bv = *reinterpret_cast<const float4*>(eptr);
        __syncthreads();    // previous tile's smem use complete
        sm.t.As[0][aCol + 0][aRow] = av.x; sm.t.As[0][aCol + 1][aRow] = av.y;
        sm.t.As[0][aCol + 2][aRow] = av.z; sm.t.As[0][aCol + 3][aRow] = av.w;
        sm.t.Bs[0][aCol + 0][aRow] = bv.x; sm.t.Bs[0][aCol + 1][aRow] = bv.y;
        sm.t.Bs[0][aCol + 2][aRow] = bv.z; sm.t.Bs[0][aCol + 3][aRow] = bv.w;
        __syncthreads();

        int buf = 0;
        for (int kk = BK; ; kk += BK) {
            const bool more = (kk < D_DIM);
            if (more) {
                av = *reinterpret_cast<const float4*>(xptr + kk);
                bv = *reinterpret_cast<const float4*>(eptr + kk);
            }
            // ---- compute on current buffer ----
            #pragma unroll
            for (int k = 0; k < BK; k++) {
                float4 a0 = *reinterpret_cast<const float4*>(&sm.t.As[buf][k][ty * 8]);
                float4 a1 = *reinterpret_cast<const float4*>(&sm.t.As[buf][k][ty * 8 + 4]);
                float4 b0 = *reinterpret_cast<const float4*>(&sm.t.Bs[buf][k][tx * 8]);
                float4 b1 = *reinterpret_cast<const float4*>(&sm.t.Bs[buf][k][tx * 8 + 4]);
                float aa[8] = {a0.x, a0.y, a0.z, a0.w, a1.x, a1.y, a1.z, a1.w};
                float bb[8] = {b0.x, b0.y, b0.z, b0.w, b1.x, b1.y, b1.z, b1.w};
                #pragma unroll
                for (int i = 0; i < 8; i++)
                    #pragma unroll
                    for (int j = 0; j < 8; j++)
                        acc[i][j] = fmaf(aa[i], bb[j], acc[i][j]);
            }
            if (!more) break;
            // ---- store next chunk into other buffer ----
            const int nb = buf ^ 1;
            sm.t.As[nb][aCol + 0][aRow] = av.x; sm.t.As[nb][aCol + 1][aRow] = av.y;
            sm.t.As[nb][aCol + 2][aRow] = av.z; sm.t.As[nb][aCol + 3][aRow] = av.w;
            sm.t.Bs[nb][aCol + 0][aRow] = bv.x; sm.t.Bs[nb][aCol + 1][aRow] = bv.y;
            sm.t.Bs[nb][aCol + 2][aRow] = bv.z; sm.t.Bs[nb][aCol + 3][aRow] = bv.w;
            __syncthreads();
            buf = nb;
        }

        // ---- fold tile into running argmin, replicating reference rounding:
        //      d = fl( fl(xn + en) - 2*dot )   (mul exact, adds rounded) ----
        #pragma unroll
        for (int j = 0; j < 8; j++) {
            const int c = ct * BN + tx * 8 + j;     // ascending per thread
            const float en = g_eNorm[c];
            #pragma unroll
            for (int i = 0; i < 8; i++) {
                float s    = __fadd_rn(xn[i], en);
                float dist = __fadd_rn(s, __fmul_rn(-2.f, acc[i][j]));
                if (dist < bestD[i]) { bestD[i] = dist; bestI[i] = c; }
            }
        }
    }

    // ---- cross-thread argmin reduce (lowest index on equal values) ----
    __syncthreads();
    #pragma unroll
    for (int i = 0; i < 8; i++) {
        sm.r.redD[ty * 8 + i][tx] = bestD[i];
        sm.r.redI[ty * 8 + i][tx] = bestI[i];
    }
    __syncthreads();
    if (tid < BM) {
        float bd = sm.r.redD[tid][0]; int bi = sm.r.redI[tid][0];
        #pragma unroll
        for (int t2 = 1; t2 < 16; t2++) {
            float d2 = sm.r.redD[tid][t2]; int i2 = sm.r.redI[tid][t2];
            if (d2 < bd || (d2 == bd && i2 < bi)) { bd = d2; bi = i2; }
        }
        g_idx[rowBase + tid] = bi;
    }
}

// ---------------------------------------------------------------------------
// Gather quantized rows, write quantized_st, accumulate SSE + histogram,
// write indices (as float) at the tail of the output buffer.
// ---------------------------------------------------------------------------
__global__ void gather_kernel(const float* __restrict__ x,
                              const float* __restrict__ emb,
                              const float* __restrict__ mask,
                              float* __restrict__ out) {
    int n = blockIdx.x;
    int t = threadIdx.x;
    int idx = g_idx[n];
    float m = mask[n];
    float e = emb[(size_t)idx * D_DIM + t];
    float q = e * m;                          // quantized (== quantized_st numerically)
    size_t off = (size_t)n * D_DIM + t;
    out[off] = q;
    float diff = q - x[off];
    float s = diff * diff;
    #pragma unroll
    for (int o = 16; o; o >>= 1) s += __shfl_down_sync(0xffffffffu, s, o);
    __shared__ float ws[8];
    if ((t & 31) == 0) ws[t >> 5] = s;
    __syncthreads();
    if (t < 8) {
        float v = ws[t];
        #pragma unroll
        for (int o = 4; o; o >>= 1) v += __shfl_down_sync(0x000000ffu, v, o);
        if (t == 0) {
            atomicAdd(&g_sse[n & 255], (double)v);
            atomicAdd(&g_hist[idx], 1u);
            out[(size_t)N_ROWS * D_DIM + 3 + n] = (float)idx;
        }
    }
}

// ---------------------------------------------------------------------------
// Finalize: losses + perplexity scalars.
// ---------------------------------------------------------------------------
__global__ void finalize_kernel(float* __restrict__ out) {
    int t = threadIdx.x;
    __shared__ double shd[256];
    __shared__ float  shf[256];

    shd[t] = g_sse[t];
    float ps = 0.f;
    const float invN = 1.0f / (float)N_ROWS;
    for (int k = t; k < K_CODES; k += 256) {
        float p = (float)g_hist[k] * invN;
        ps += p * logf(p + 1e-8f);
    }
    shf[t] = ps;
    __syncthreads();
    for (int o = 128; o; o >>= 1) {
        if (t < o) { shd[t] += shd[t + o]; shf[t] += shf[t + o]; }
        __syncthreads();
    }
    if (t == 0) {
        float e = (float)(shd[0] / ((double)N_ROWS * (double)D_DIM));
        size_t base = (size_t)N_ROWS * D_DIM;
        out[base + 0] = 0.25f * e;     // commitment_loss
        out[base + 1] = e;             // q_latent_loss (== e_latent numerically)
        out[base + 2] = expf(-shf[0]); // perplexity
    }
}

// ---------------------------------------------------------------------------
extern "C" void kernel_launch(void* const* d_in, const int* in_sizes, int n_in,
                              void* d_out, int out_size) {
    const float* x    = (const float*)d_in[0];   // [32768, 256]
    const float* emb  = (const float*)d_in[1];   // [4096, 256]
    const float* mask = (const float*)d_in[2];   // [32768]
    float* out = (float*)d_out;

    reset_kernel<<<16, 256>>>();
    xnorm_kernel<<<N_ROWS / 8, 256>>>(x);
    enorm_kernel<<<K_CODES / 8, 256>>>(emb);
    argmin_kernel<<<N_ROWS / 128, 256>>>(x, emb);
    gather_kernel<<<N_ROWS, 256>>>(x, emb, mask, out);
    finalize_kernel<<<1, 256>>>(out);
}

// round 14
// speedup vs baseline: 1.0367x; 1.0367x over previous
#include <cuda_runtime.h>
#include <math.h>

#define N_ROWS  32768
#define D_DIM   256
#define K_CODES 4096

typedef unsigned long long u64;

// Scratch (no allocations allowed): device globals.
__device__ float        g_eNorm[K_CODES];
__device__ float        g_xNorm[N_ROWS];
__device__ int          g_idx[N_ROWS];
__device__ unsigned int g_hist[K_CODES];
__device__ double       g_sse[256];

// ---- packed fp32x2 helpers (FFMA2: ptxas never emits this from C++) ------
__device__ __forceinline__ void ffma2(u64& d, u64 a, u64 b) {
    asm("fma.rn.f32x2 %0, %1, %2, %0;" : "+l"(d) : "l"(a), "l"(b));
}
__device__ __forceinline__ u64 rep2(float v) {
    u64 r; asm("mov.b64 %0, {%1, %1};" : "=l"(r) : "f"(v)); return r;
}
__device__ __forceinline__ void unpack2(u64 v, float& lo, float& hi) {
    asm("mov.b64 {%0, %1}, %2;" : "=f"(lo), "=f"(hi) : "l"(v));
}

// ---------------------------------------------------------------------------
// Reset accumulated scratch (graph replays must be deterministic)
// ---------------------------------------------------------------------------
__global__ void reset_kernel() {
    int t = blockIdx.x * blockDim.x + threadIdx.x;
    for (int k = t; k < K_CODES; k += gridDim.x * blockDim.x) g_hist[k] = 0u;
    if (t < 256) g_sse[t] = 0.0;
}

// ---------------------------------------------------------------------------
// xNorm[n] = sum_d x[n][d]^2 — emulates XLA GPU row reduction (validated R6):
// warp/row, float2 loads, per-lane accumulators, shfl_down tree. No fma.
// ---------------------------------------------------------------------------
__global__ void xnorm_kernel(const float* __restrict__ x) {
    int warp = (blockIdx.x * blockDim.x + threadIdx.x) >> 5;
    int lane = threadIdx.x & 31;
    if (warp >= N_ROWS) return;
    const float2* xr = reinterpret_cast<const float2*>(x + (size_t)warp * D_DIM);
    float a0 = 0.f, a1 = 0.f;
    #pragma unroll
    for (int j = 0; j < 4; j++) {
        float2 v = xr[j * 32 + lane];
        a0 = __fadd_rn(a0, __fmul_rn(v.x, v.x));
        a1 = __fadd_rn(a1, __fmul_rn(v.y, v.y));
    }
    float s = __fadd_rn(a0, a1);
    #pragma unroll
    for (int o = 16; o; o >>= 1)
        s = __fadd_rn(s, __shfl_down_sync(0xffffffffu, s, o));
    if (lane == 0) g_xNorm[warp] = s;
}

// ---------------------------------------------------------------------------
// eNorm[k] = sum_d emb[k][d]^2 (value ~5e-6 — below half-ulp of xNorm).
// ---------------------------------------------------------------------------
__global__ void enorm_kernel(const float* __restrict__ emb) {
    int warp = (blockIdx.x * blockDim.x + threadIdx.x) >> 5;
    int lane = threadIdx.x & 31;
    if (warp >= K_CODES) return;
    const float2* er = reinterpret_cast<const float2*>(emb + (size_t)warp * D_DIM);
    float a0 = 0.f, a1 = 0.f;
    #pragma unroll
    for (int j = 0; j < 4; j++) {
        float2 v = er[j * 32 + lane];
        a0 = __fadd_rn(a0, __fmul_rn(v.x, v.x));
        a1 = __fadd_rn(a1, __fmul_rn(v.y, v.y));
    }
    float s = __fadd_rn(a0, a1);
    #pragma unroll
    for (int o = 16; o; o >>= 1)
        s = __fadd_rn(s, __shfl_down_sync(0xffffffffu, s, o));
    if (lane == 0) g_eNorm[warp] = s;
}

// ---------------------------------------------------------------------------
// Main kernel: argmin_k fl( fl(xNorm+eNorm) - 2*dot ), full fp32 dot.
// R6 ncu: 46.2% fma at ~scalar-FFMA peak => fp32 pipe is 2x wide via packed
// fma.rn.f32x2. Pack accumulators along ROWS: acc2[i2][j] = rows (2*i2,2*i2+1).
// A-pairs load directly as 16B ulonglong2 from transposed As; B replicated
// via one mov.b64 per scalar, consumed immediately (register pressure ~115).
// Per-lane results bit-identical to R6's scalar FFMA kernel.
// ---------------------------------------------------------------------------
__global__ void __launch_bounds__(256, 2)
argmin_kernel(const float* __restrict__ x, const float* __restrict__ emb) {
    constexpr int BM = 128, BN = 128, BK = 8;
    constexpr int LD = BM + 4;

    __shared__ union {
        struct { float As[2][BK][LD]; float Bs[2][BK][LD]; } t;
        struct { float redD[BM][17];  int   redI[BM][17]; }  r;
    } sm;

    const int tid = threadIdx.x;
    const int tx  = tid & 15;               // code group  (0..15) -> 8 codes
    const int ty  = tid >> 4;               // row  group  (0..15) -> 8 rows
    const int rowBase = blockIdx.x * BM;

    const int aRow = tid >> 1;              // 0..127
    const int aCol = (tid & 1) * 4;         // 0 or 4

    float bestD[8];
    int   bestI[8];
    float xn[8];
    #pragma unroll
    for (int i = 0; i < 8; i++) {
        bestD[i] = INFINITY; bestI[i] = 0;
        xn[i] = g_xNorm[rowBase + ty * 8 + i];
    }

    const float* xptr = x + (size_t)(rowBase + aRow) * D_DIM + aCol;

    for (int ct = 0; ct < K_CODES / BN; ++ct) {
        const float* eptr = emb + (size_t)(ct * BN + aRow) * D_DIM + aCol;

        u64 acc2[4][8];                     // rows (2*i2, 2*i2+1) x 8 codes
        #pragma unroll
        for (int i = 0; i < 4; i++)
            #pragma unroll
            for (int j = 0; j < 8; j++) acc2[i][j] = 0ull;

        // ---- preload chunk 0 into buffer 0 ----
        float4 av = *reinterpret_cast<const float4*>(xptr);
        float4 bv = *reinterpret_cast<const float4*>(eptr);
        __syncthreads();    // previous tile's smem use complete
        sm.t.As[0][aCol + 0][aRow] = av.x; sm.t.As[0][aCol + 1][aRow] = av.y;
        sm.t.As[0][aCol + 2][aRow] = av.z; sm.t.As[0][aCol + 3][aRow] = av.w;
        sm.t.Bs[0][aCol + 0][aRow] = bv.x; sm.t.Bs[0][aCol + 1][aRow] = bv.y;
        sm.t.Bs[0][aCol + 2][aRow] = bv.z; sm.t.Bs[0][aCol + 3][aRow] = bv.w;
        __syncthreads();

        int buf = 0;
        for (int kk = BK; ; kk += BK) {
            const bool more = (kk < D_DIM);
            if (more) {
                av = *reinterpret_cast<const float4*>(xptr + kk);
                bv = *reinterpret_cast<const float4*>(eptr + kk);
            }
            // ---- compute on current buffer (packed f32x2) ----
            #pragma unroll
            for (int k = 0; k < BK; k++) {
                const ulonglong2* ap =
                    reinterpret_cast<const ulonglong2*>(&sm.t.As[buf][k][ty * 8]);
                ulonglong2 aA = ap[0];      // rows (0,1),(2,3) of this thread
                ulonglong2 aB = ap[1];      // rows (4,5),(6,7)
                u64 aa2[4] = {aA.x, aA.y, aB.x, aB.y};
                float4 b0 = *reinterpret_cast<const float4*>(&sm.t.Bs[buf][k][tx * 8]);
                float4 b1 = *reinterpret_cast<const float4*>(&sm.t.Bs[buf][k][tx * 8 + 4]);
                float bb[8] = {b0.x, b0.y, b0.z, b0.w, b1.x, b1.y, b1.z, b1.w};
                #pragma unroll
                for (int j = 0; j < 8; j++) {
                    u64 br = rep2(bb[j]);
                    #pragma unroll
                    for (int i = 0; i < 4; i++)
                        ffma2(acc2[i][j], aa2[i], br);
                }
            }
            if (!more) break;
            // ---- store next chunk into other buffer ----
            const int nb = buf ^ 1;
            sm.t.As[nb][aCol + 0][aRow] = av.x; sm.t.As[nb][aCol + 1][aRow] = av.y;
            sm.t.As[nb][aCol + 2][aRow] = av.z; sm.t.As[nb][aCol + 3][aRow] = av.w;
            sm.t.Bs[nb][aCol + 0][aRow] = bv.x; sm.t.Bs[nb][aCol + 1][aRow] = bv.y;
            sm.t.Bs[nb][aCol + 2][aRow] = bv.z; sm.t.Bs[nb][aCol + 3][aRow] = bv.w;
            __syncthreads();
            buf = nb;
        }

        // ---- fold tile into running argmin, replicating reference rounding:
        //      d = fl( fl(xn + en) - 2*dot )   (mul exact, adds rounded) ----
        #pragma unroll
        for (int j = 0; j < 8; j++) {
            const int c = ct * BN + tx * 8 + j;     // ascending per thread
            const float en = g_eNorm[c];
            #pragma unroll
            for (int i2 = 0; i2 < 4; i2++) {
                float dlo, dhi;
                unpack2(acc2[i2][j], dlo, dhi);
                float s0 = __fadd_rn(xn[2 * i2], en);
                float d0 = __fadd_rn(s0, __fmul_rn(-2.f, dlo));
                if (d0 < bestD[2 * i2]) { bestD[2 * i2] = d0; bestI[2 * i2] = c; }
                float s1 = __fadd_rn(xn[2 * i2 + 1], en);
                float d1 = __fadd_rn(s1, __fmul_rn(-2.f, dhi));
                if (d1 < bestD[2 * i2 + 1]) { bestD[2 * i2 + 1] = d1; bestI[2 * i2 + 1] = c; }
            }
        }
    }

    // ---- cross-thread argmin reduce (lowest index on equal values) ----
    __syncthreads();
    #pragma unroll
    for (int i = 0; i < 8; i++) {
        sm.r.redD[ty * 8 + i][tx] = bestD[i];
        sm.r.redI[ty * 8 + i][tx] = bestI[i];
    }
    __syncthreads();
    if (tid < BM) {
        float bd = sm.r.redD[tid][0]; int bi = sm.r.redI[tid][0];
        #pragma unroll
        for (int t2 = 1; t2 < 16; t2++) {
            float d2 = sm.r.redD[tid][t2]; int i2 = sm.r.redI[tid][t2];
            if (d2 < bd || (d2 == bd && i2 < bi)) { bd = d2; bi = i2; }
        }
        g_idx[rowBase + tid] = bi;
    }
}

// ---------------------------------------------------------------------------
// Gather quantized rows, write quantized_st, accumulate SSE + histogram,
// write indices (as float) at the tail of the output buffer.
// ---------------------------------------------------------------------------
__global__ void gather_kernel(const float* __restrict__ x,
                              const float* __restrict__ emb,
                              const float* __restrict__ mask,
                              float* __restrict__ out) {
    int n = blockIdx.x;
    int t = threadIdx.x;
    int idx = g_idx[n];
    float m = mask[n];
    float e = emb[(size_t)idx * D_DIM + t];
    float q = e * m;                          // quantized (== quantized_st numerically)
    size_t off = (size_t)n * D_DIM + t;
    out[off] = q;
    float diff = q - x[off];
    float s = diff * diff;
    #pragma unroll
    for (int o = 16; o; o >>= 1) s += __shfl_down_sync(0xffffffffu, s, o);
    __shared__ float ws[8];
    if ((t & 31) == 0) ws[t >> 5] = s;
    __syncthreads();
    if (t < 8) {
        float v = ws[t];
        #pragma unroll
        for (int o = 4; o; o >>= 1) v += __shfl_down_sync(0x000000ffu, v, o);
        if (t == 0) {
            atomicAdd(&g_sse[n & 255], (double)v);
            atomicAdd(&g_hist[idx], 1u);
            out[(size_t)N_ROWS * D_DIM + 3 + n] = (float)idx;
        }
    }
}

// ---------------------------------------------------------------------------
// Finalize: losses + perplexity scalars (perplexity sum in double for margin).
// ---------------------------------------------------------------------------
__global__ void finalize_kernel(float* __restrict__ out) {
    int t = threadIdx.x;
    __shared__ double shd[256];
    __shared__ double shp[256];

    shd[t] = g_sse[t];
    double ps = 0.0;
    const double invN = 1.0 / (double)N_ROWS;
    for (int k = t; k < K_CODES; k += 256) {
        double p = (double)g_hist[k] * invN;
        ps += p * log(p + 1e-8);
    }
    shp[t] = ps;
    __syncthreads();
    for (int o = 128; o; o >>= 1) {
        if (t < o) { shd[t] += shd[t + o]; shp[t] += shp[t + o]; }
        __syncthreads();
    }
    if (t == 0) {
        float e = (float)(shd[0] / ((double)N_ROWS * (double)D_DIM));
        size_t base = (size_t)N_ROWS * D_DIM;
        out[base + 0] = 0.25f * e;          // commitment_loss
        out[base + 1] = e;                  // q_latent_loss (== e_latent numerically)
        out[base + 2] = (float)exp(-shp[0]); // perplexity
    }
}

// ---------------------------------------------------------------------------
extern "C" void kernel_launch(void* const* d_in, const int* in_sizes, int n_in,
                              void* d_out, int out_size) {
    const float* x    = (const float*)d_in[0];   // [32768, 256]
    const float* emb  = (const float*)d_in[1];   // [4096, 256]
    const float* mask = (const float*)d_in[2];   // [32768]
    float* out = (float*)d_out;

    reset_kernel<<<16, 256>>>();
    xnorm_kernel<<<N_ROWS / 8, 256>>>(x);
    enorm_kernel<<<K_CODES / 8, 256>>>(emb);
    argmin_kernel<<<N_ROWS / 128, 256>>>(x, emb);
    gather_kernel<<<N_ROWS, 256>>>(x, emb, mask, out);
    finalize_kernel<<<1, 256>>>(out);
}